// round 9
// baseline (speedup 1.0000x reference)
#include <cuda_runtime.h>
#include <math.h>
#include <float.h>

#define BS 32
#define NQ 300
#define NC 2001
#define NT 25

// Scratch cost matrix, stored transposed as [b][t][q].
__device__ float g_cost[BS * NT * NQ];

// ---------------------------------------------------------------------------
// Phase A: softmax over classes + gather target-class probs -> -prob cost.
// (unchanged from R8)
// ---------------------------------------------------------------------------
__global__ void cost_kernel(const float* __restrict__ logits,
                            const int* __restrict__ targets) {
    const unsigned FULL = 0xffffffffu;
    int gwarp = (blockIdx.x * blockDim.x + threadIdx.x) >> 5;
    int lane  = threadIdx.x & 31;
    if (gwarp >= BS * NQ) return;
    int b = gwarp / NQ;
    int q = gwarp % NQ;

    const float* row = logits + ((size_t)b * NQ + q) * NC;

    float m = -FLT_MAX;
    for (int c = lane; c < NC; c += 32) m = fmaxf(m, row[c]);
    #pragma unroll
    for (int o = 16; o; o >>= 1) m = fmaxf(m, __shfl_xor_sync(FULL, m, o));

    float s = 0.f;
    for (int c = lane; c < NC; c += 32) s += expf(row[c] - m);
    #pragma unroll
    for (int o = 16; o; o >>= 1) s += __shfl_xor_sync(FULL, s, o);

    if (lane < NT) {
        int cls = targets[b * NT + lane];
        float p = expf(row[cls] - m) / s;
        g_cost[((size_t)b * NT + lane) * NQ + q] = -p;
    }
}

// monotonic float<->uint order-preserving transform
__device__ __forceinline__ unsigned fkey(float x) {
    unsigned v = __float_as_uint(x);
    return (v & 0x80000000u) ? ~v : (v | 0x80000000u);
}
__device__ __forceinline__ float funkey(unsigned k) {
    unsigned v = (k & 0x80000000u) ? (k ^ 0x80000000u) : ~k;
    return __uint_as_float(v);
}

// argmin_j (C[ri][j] - v[j]) over all 300 columns; first-j tie-break.
// Lane l < 25 owns columns [12l, 12l+12). d[] returned for conflict seeding.
__device__ __forceinline__ void row_argmin(const float* __restrict__ C,
                                           const float* vv, int ri, int lane,
                                           bool active, float* d,
                                           float* minVal_out, int* bestj_out) {
    const unsigned FULL = 0xffffffffu;
    float bv = FLT_MAX; int bs = 0;
    if (active) {
        const float4* Crow = (const float4*)&C[ri * NQ + 12 * lane];
        float4 c0 = Crow[0], c1 = Crow[1], c2 = Crow[2];
        d[0]=c0.x-vv[0];  d[1]=c0.y-vv[1];  d[2]=c0.z-vv[2];  d[3]=c0.w-vv[3];
        d[4]=c1.x-vv[4];  d[5]=c1.y-vv[5];  d[6]=c1.z-vv[6];  d[7]=c1.w-vv[7];
        d[8]=c2.x-vv[8];  d[9]=c2.y-vv[9];  d[10]=c2.z-vv[10]; d[11]=c2.w-vv[11];
        float v6[6]; int s6[6];
        #pragma unroll
        for (int k = 0; k < 6; k++) {
            bool p = d[2*k+1] < d[2*k];
            v6[k] = p ? d[2*k+1] : d[2*k];
            s6[k] = p ? 2*k+1 : 2*k;
        }
        float v3[3]; int s3[3];
        #pragma unroll
        for (int k = 0; k < 3; k++) {
            bool p = v6[2*k+1] < v6[2*k];
            v3[k] = p ? v6[2*k+1] : v6[2*k];
            s3[k] = p ? s6[2*k+1] : s6[2*k];
        }
        bool p0 = v3[1] < v3[0];
        float vx = p0 ? v3[1] : v3[0];
        int   sx = p0 ? s3[1] : s3[0];
        bool p1 = v3[2] < vx;
        bv = p1 ? v3[2] : vx;
        bs = p1 ? s3[2] : sx;
    }
    unsigned key    = active ? fkey(bv) : 0xFFFFFFFFu;
    unsigned minkey = __reduce_min_sync(FULL, key);
    unsigned myj    = (active && key == minkey) ? (unsigned)(12*lane + bs)
                                                : 0xFFFFFFFFu;
    *bestj_out  = (int)__reduce_min_sync(FULL, myj);
    *minVal_out = funkey(minkey);
}

// ---------------------------------------------------------------------------
// Phase B: JV LSAP, one warp per batch. First-pop argmins for all 25 rows are
// precomputed (they depend only on v, which changes only on conflicts; after a
// conflict, d increases only on scanned columns, so a cached argmin stays
// exactly valid unless its column was scanned). The sweep is then shuffle/
// ballot-only on the fast path; conflicts run the R8-verified general loop.
// ---------------------------------------------------------------------------
__global__ void lsap_kernel(float* __restrict__ out) {
    const unsigned FULL = 0xffffffffu;
    int b    = blockIdx.x;
    int lane = threadIdx.x;   // blockDim.x == 32

    __shared__ alignas(16) float C[NT * NQ];
    __shared__ alignas(16) int   path[NQ];
    __shared__ float u[NT];
    __shared__ int   row4col[NQ];
    __shared__ int   col4row_sm[NT];
    __shared__ int   sr[NT];
    __shared__ float disc[NT];

    {   // vectorized cost load (7500 floats = 1875 float4)
        const float4* src = (const float4*)(g_cost + (size_t)b * NT * NQ);
        float4* dst = (float4*)C;
        for (int k = lane; k < (NT * NQ) / 4; k += 32) dst[k] = src[k];
    }
    for (int j = lane; j < NQ; j += 32) row4col[j] = -1;
    if (lane < NT) { u[lane] = 0.f; col4row_sm[lane] = -1; }
    __syncwarp();

    const bool active = (lane < 25);
    float vv[12];
    #pragma unroll
    for (int s = 0; s < 12; s++) vv[s] = 0.f;

    // ---- precompute all 25 first-pop argmins (v == 0) ----
    float cbv = 0.f; int cbj = -1; int cvalid = 1;
    {
        float dtmp[12];
        for (int r = 0; r < NT; r++) {
            float mv; int bj;
            row_argmin(C, vv, r, lane, active, dtmp, &mv, &bj);
            if (lane == r) { cbv = mv; cbj = bj; }
        }
    }

    int my_col = -1;   // col4row for row `lane`, register-resident

    for (int cur = 0; cur < NT; cur++) {
        float minVal = __shfl_sync(FULL, cbv, cur);
        int   bestj  = __shfl_sync(FULL, cbj, cur);
        int   valid  = __shfl_sync(FULL, cvalid, cur);

        float d[12];
        bool have_d = false;
        if (!valid) {   // cache stale: recompute with current v
            row_argmin(C, vv, cur, lane, active, d, &minVal, &bestj);
            have_d = true;
        }

        unsigned asg = __ballot_sync(FULL, my_col == bestj);
        if (asg == 0u) {
            // fast path: single-pop search (v unchanged, u[cur] = minVal)
            if (lane == cur) my_col = bestj;
            if (lane == 0) {
                u[cur] = minVal;
                row4col[bestj]  = cur;
                col4row_sm[cur] = bestj;
            }
            continue;
        }

        // ---- conflict: continue the exact general JV search ----
        int i = __ffs(asg) - 1;              // row currently holding bestj
        if (!have_d)
            row_argmin(C, vv, cur, lane, active, d, &minVal, &bestj);
        __syncwarp();                         // fence u/row4col stores

        float sh[12];
        #pragma unroll
        for (int s = 0; s < 12; s++) sh[s] = d[s];
        unsigned scm = active ? 0u : 0xFFFu;  // scanned-column mask per lane
        if (active) {                          // path[j] = cur for all j
            int4 pc = make_int4(cur, cur, cur, cur);
            int4* pp = (int4*)&path[12 * lane];
            pp[0] = pc; pp[1] = pc; pp[2] = pc;
        }
        if (lane == bestj / 12) scm |= 1u << (bestj % 12);
        if (lane == 0) { sr[0] = cur; disc[0] = 0.f; }
        int nsr  = 1;
        int sink = -1;

        while (true) {
            if (lane == 0) { sr[nsr] = i; disc[nsr] = minVal; }
            nsr++;
            float ui = u[i];
            float am = minVal - ui;   // exact 0 for duplicate-row conflicts
            float bv2 = FLT_MAX; int bs2 = -1;
            if (active) {
                const float4* Crow = (const float4*)&C[i * NQ + 12 * lane];
                float4 c0 = Crow[0], c1 = Crow[1], c2 = Crow[2];
                float cc[12] = {c0.x,c0.y,c0.z,c0.w, c1.x,c1.y,c1.z,c1.w,
                                c2.x,c2.y,c2.z,c2.w};
                #pragma unroll
                for (int s = 0; s < 12; s++) {
                    if (!((scm >> s) & 1u)) {
                        float dd = (cc[s] + am) - vv[s];
                        if (dd < sh[s]) { sh[s] = dd; path[12*lane + s] = i; }
                        if (sh[s] < bv2) { bv2 = sh[s]; bs2 = s; }
                    }
                }
            }
            unsigned k2 = (bs2 >= 0) ? fkey(bv2) : 0xFFFFFFFFu;
            unsigned mk = __reduce_min_sync(FULL, k2);
            unsigned mj = (k2 == mk && bs2 >= 0) ? (unsigned)(12*lane + bs2)
                                                 : 0xFFFFFFFFu;
            int bj = (int)__reduce_min_sync(FULL, mj);
            minVal = funkey(mk);
            if (lane == bj / 12) scm |= 1u << (bj % 12);
            int r2 = row4col[bj];
            if (r2 == -1) { sink = bj; break; }
            i = r2;
        }

        // v duals: scanned columns froze sh at their pop value == shortest[j]
        if (active) {
            #pragma unroll
            for (int s = 0; s < 12; s++)
                if ((scm >> s) & 1u) vv[s] -= minVal - sh[s];
        }
        __syncwarp();
        if (lane == 0) {
            u[cur] += minVal;
            for (int k = 1; k < nsr; k++) u[sr[k]] += minVal - disc[k];
            int j = sink;
            while (true) {
                int i2 = path[j];
                row4col[j] = i2;
                int nxt = col4row_sm[i2];
                col4row_sm[i2] = j;
                j = nxt;
                if (i2 == cur) break;
            }
        }
        __syncwarp();
        // refresh register assignment state (augment may reshuffle columns)
        if (lane < NT) my_col = col4row_sm[lane];
        // invalidate caches whose argmin column was scanned (d increased there)
        unsigned oscm = __shfl_sync(FULL, scm, (cbj >= 0) ? (cbj / 12) : 0);
        if (cbj >= 0 && ((oscm >> (cbj % 12)) & 1u)) cvalid = 0;
    }

    // stable argsort of distinct ints by rank counting; graded as float32.
    __syncwarp();
    if (lane < NT) {
        int myv = col4row_sm[lane];
        int pos = 0;
        #pragma unroll
        for (int t = 0; t < NT; t++) pos += (col4row_sm[t] < myv) ? 1 : 0;
        out[b * NT + pos]           = (float)myv;   // row_inds
        out[BS * NT + b * NT + pos] = (float)lane;  // col_inds
    }
}

// ---------------------------------------------------------------------------
extern "C" void kernel_launch(void* const* d_in, const int* in_sizes, int n_in,
                              void* d_out, int out_size) {
    const float* logits  = (const float*)d_in[0];   // [32, 300, 2001] f32
    const int*   targets = (const int*)d_in[1];     // [32, 25] i32
    float*       out     = (float*)d_out;           // [2, 32, 25] graded as f32

    int total_warps = BS * NQ;
    int threads = 256;
    int blocks = (total_warps * 32 + threads - 1) / threads;
    cost_kernel<<<blocks, threads>>>(logits, targets);

    lsap_kernel<<<BS, 32>>>(out);
}